// round 12
// baseline (speedup 1.0000x reference)
#include <cuda_runtime.h>
#include <cuda_fp16.h>
#include <cstdint>

// ---------------------------------------------------------------------------
// Problem constants
// ---------------------------------------------------------------------------
#define NTOK   16384      // B*S
#define DMODEL 1024
#define NH     16
#define DH     64
#define SEGLEN 64
#define NSEG   64
#define SLEN   4096
#define NBATCH 4
#define NEGINF -1e10f
#define GGRID  296        // persistent GEMM grid (2 per SM)

// ---------------------------------------------------------------------------
// Scratch (device globals)
// ---------------------------------------------------------------------------
__device__ __half g_qkvh[3 * NTOK * DMODEL];  // q | k | v fp16
__device__ __half g_rah [NTOK * DMODEL];      // row_attn fp16
__device__ __half g_k2h [NTOK * DMODEL];      // key_row2 fp16
__device__ __half g_ah  [NTOK * DMODEL];      // generic fp16 activation
__device__ __half g_lah [NTOK * DMODEL];      // unnormalized masked-local P@V (fp16)
__device__ float  g_kt  [NTOK * DMODEL];      // key_row f32 (pre-LN)
__device__ float  g_mloc[NTOK * NH];
__device__ float  g_sloc[NTOK * NH];

// Pre-transposed fp16 weights: [6][N=1024][K=1024] (Wq pre-scaled by 0.125)
__device__ __half g_w16[6][DMODEL * DMODEL];

// ---------------------------------------------------------------------------
// Helpers
// ---------------------------------------------------------------------------
__device__ __forceinline__ uint32_t smem_u32(const void* p) {
    uint32_t a;
    asm("{ .reg .u64 t; cvta.to.shared.u64 t, %1; cvt.u32.u64 %0, t; }"
        : "=r"(a) : "l"(p));
    return a;
}
__device__ __forceinline__ void cpasync16(uint32_t s, const void* g) {
    asm volatile("cp.async.cg.shared.global [%0], [%1], 16;" :: "r"(s), "l"(g));
}
#define CP_COMMIT() asm volatile("cp.async.commit_group;")
#define CP_WAIT1()  asm volatile("cp.async.wait_group 1;")
#define CP_WAIT0()  asm volatile("cp.async.wait_group 0;")

#define LDSM4(r0, r1, r2, r3, addr) \
    asm volatile("ldmatrix.sync.aligned.m8n8.x4.shared.b16 {%0,%1,%2,%3}, [%4];" \
                 : "=r"(r0), "=r"(r1), "=r"(r2), "=r"(r3) : "r"(addr))
#define LDSM4T(r0, r1, r2, r3, addr) \
    asm volatile("ldmatrix.sync.aligned.m8n8.x4.trans.shared.b16 {%0,%1,%2,%3}, [%4];" \
                 : "=r"(r0), "=r"(r1), "=r"(r2), "=r"(r3) : "r"(addr))

#define MMA16816(c0, c1, c2, c3, a0, a1, a2, a3, b0, b1) \
    asm volatile("mma.sync.aligned.m16n8k16.row.col.f32.f16.f16.f32 " \
                 "{%0,%1,%2,%3}, {%4,%5,%6,%7}, {%8,%9}, {%0,%1,%2,%3};" \
                 : "+f"(c0), "+f"(c1), "+f"(c2), "+f"(c3) \
                 : "r"(a0), "r"(a1), "r"(a2), "r"(a3), "r"(b0), "r"(b1))

__device__ __forceinline__ uint32_t hb(float v) {
    return (uint32_t)__half_as_ushort(__float2half(v));
}

// ---------------------------------------------------------------------------
// Weight transpose + fp16 convert (with scale):  W[K][N] -> T[N][K] fp16
// ---------------------------------------------------------------------------
__global__ __launch_bounds__(256) void wprep_k(const float* __restrict__ W,
                                               __half* __restrict__ T,
                                               float scale)
{
    __shared__ float t[32][33];
    int bn = blockIdx.x * 32;
    int bk = blockIdx.y * 32;
    int x = threadIdx.x & 31;
    int y = threadIdx.x >> 5;
    #pragma unroll
    for (int i = 0; i < 32; i += 8)
        t[y + i][x] = W[(size_t)(bk + y + i) * DMODEL + bn + x];
    __syncthreads();
    #pragma unroll
    for (int i = 0; i < 32; i += 8) {
        float v = t[x][y + i] * scale;
        T[(size_t)(bn + y + i) * DMODEL + bk + x] = __float2half(v);
    }
}

// ---------------------------------------------------------------------------
// Activation fp32 -> fp16 convert (only used for the input x)
// ---------------------------------------------------------------------------
__global__ __launch_bounds__(256) void aconv_k(const float* __restrict__ in,
                                               __half* __restrict__ oh)
{
    size_t i = ((size_t)blockIdx.x * 256 + threadIdx.x) * 4;
    float4 v = *(const float4*)(in + i);
    *(uint2*)(oh + i) = make_uint2(hb(v.x) | (hb(v.y) << 16),
                                   hb(v.z) | (hb(v.w) << 16));
}

// ---------------------------------------------------------------------------
// Persistent tensor-core GEMM (pure fp16, fp32 accumulate).  BK=64.
//   tN = t % tilesX, tM = t / tilesX.
// ---------------------------------------------------------------------------
#define GBK    64
#define GPITCH 72                      // fp16 elements per smem row (144 B, padded)
#define GTILE_B (128 * GPITCH * 2)     // 18432 B per tile
#define GSTAGE_B (2 * GTILE_B)         // A, B = 36864 B
#define GSMEM   (3 * GSTAGE_B)         // 3 stages = 110592 B

template<bool HALF_OUT>
__global__ __launch_bounds__(256) void gemm_mma(
    const __half* __restrict__ Ah,
    const __half* __restrict__ Bf,
    const float* __restrict__ res, void* __restrict__ Cv, size_t matStride,
    int tilesX, int tilesTotal)
{
    extern __shared__ char dsm[];
    const uint32_t sb = smem_u32(dsm);

    const int tid  = threadIdx.x;
    const int wid  = tid >> 5;
    const int lane = tid & 31;
    const int wm = wid & 1;
    const int wn = wid >> 1;
    const int r0 = tid >> 1;              // 0..127
    const int cb0 = (tid & 1) * 32;       // element col base within chunk
    const int a_row = (lane & 15);
    const int a_kh  = (lane >> 4) * 8;
    const int b_row = (lane & 7) + ((lane >> 4) << 3);
    const int b_kh  = ((lane >> 3) & 1) * 8;

    for (int t = blockIdx.x; t < tilesTotal; t += gridDim.x) {
        const int tN = t % tilesX, tM = t / tilesX;
        const __half* Ahp = Ah + (size_t)(tM * 128) * DMODEL;
        const __half* Bp  = Bf + (size_t)(tN * 128) * DMODEL;

        float acc[4][4][4];
        #pragma unroll
        for (int i = 0; i < 4; i++)
            #pragma unroll
            for (int j = 0; j < 4; j++)
                #pragma unroll
                for (int tt = 0; tt < 4; tt++) acc[i][j][tt] = 0.0f;

        auto issue_chunk = [&](int c, int st) {
            const int k0 = c * GBK;
            uint32_t s = sb + st * GSTAGE_B;
            #pragma unroll
            for (int i = 0; i < 4; i++) {
                uint32_t so = (uint32_t)(r0 * (GPITCH * 2) + (cb0 + i * 8) * 2);
                size_t go = (size_t)r0 * DMODEL + (k0 + cb0 + i * 8);
                cpasync16(s + 0 * GTILE_B + so, Ahp + go);
                cpasync16(s + 1 * GTILE_B + so, Bp  + go);
            }
            CP_COMMIT();
        };

        issue_chunk(0, 0);
        issue_chunk(1, 1);

        const int NC = DMODEL / GBK;   // 16
        for (int c = 0; c < NC; c++) {
            const int st = c % 3;
            if (c + 1 < NC) CP_WAIT1(); else CP_WAIT0();
            __syncthreads();
            if (c + 2 < NC) issue_chunk(c + 2, (c + 2) % 3);

            uint32_t sA = sb + st * GSTAGE_B;
            uint32_t sB = sA + GTILE_B;

            #pragma unroll
            for (int ks = 0; ks < 4; ks++) {
                const int kb = ks * 16;
                uint32_t aa[4][4], bbr[4][2];
                #pragma unroll
                for (int mt = 0; mt < 4; mt++) {
                    uint32_t off = (uint32_t)((wm * 64 + mt * 16 + a_row) * (GPITCH * 2)
                                              + (kb + a_kh) * 2);
                    LDSM4(aa[mt][0], aa[mt][1], aa[mt][2], aa[mt][3], sA + off);
                }
                #pragma unroll
                for (int j = 0; j < 2; j++) {
                    uint32_t off = (uint32_t)((wn * 32 + j * 16 + b_row) * (GPITCH * 2)
                                              + (kb + b_kh) * 2);
                    LDSM4(bbr[2*j][0], bbr[2*j][1], bbr[2*j+1][0], bbr[2*j+1][1], sB + off);
                }
                #pragma unroll
                for (int mt = 0; mt < 4; mt++)
                    #pragma unroll
                    for (int nt = 0; nt < 4; nt++)
                        MMA16816(acc[mt][nt][0], acc[mt][nt][1], acc[mt][nt][2], acc[mt][nt][3],
                                 aa[mt][0], aa[mt][1], aa[mt][2], aa[mt][3],
                                 bbr[nt][0], bbr[nt][1]);
            }
        }

        // Epilogue
        const int colb = (tN & 7) * 128;
        #pragma unroll
        for (int mt = 0; mt < 4; mt++) {
            #pragma unroll
            for (int nt = 0; nt < 4; nt++) {
                int row = tM * 128 + wm * 64 + mt * 16 + (lane >> 2);
                int col = colb + wn * 32 + nt * 8 + (lane & 3) * 2;
                #pragma unroll
                for (int hh = 0; hh < 2; hh++) {
                    size_t o = (size_t)(row + hh * 8) * DMODEL + col;
                    float vx = acc[mt][nt][hh * 2 + 0];
                    float vy = acc[mt][nt][hh * 2 + 1];
                    if (HALF_OUT) {
                        __half* Cb = (__half*)Cv + (size_t)(tN >> 3) * matStride;
                        *(__half2*)(Cb + o) = __floats2half2_rn(vx, vy);
                    } else {
                        float* Cb = (float*)Cv + (size_t)(tN >> 3) * matStride;
                        if (res) {
                            float2 rr = *(const float2*)(res + o);
                            vx += rr.x; vy += rr.y;
                        }
                        *(float2*)(Cb + o) = make_float2(vx, vy);
                    }
                }
            }
        }
        __syncthreads();   // guard smem reuse by next tile
    }
}

// ---------------------------------------------------------------------------
// Warp utils
// ---------------------------------------------------------------------------
__device__ __forceinline__ float warp_max(float v) {
    #pragma unroll
    for (int o = 16; o > 0; o >>= 1) v = fmaxf(v, __shfl_xor_sync(0xffffffffu, v, o));
    return v;
}
__device__ __forceinline__ float warp_sum(float v) {
    #pragma unroll
    for (int o = 16; o > 0; o >>= 1) v += __shfl_xor_sync(0xffffffffu, v, o);
    return v;
}

// ---------------------------------------------------------------------------
// Attention smem layout (dynamic, 46080 B)
// ---------------------------------------------------------------------------
#define HPI 72           // half pitch (144 B rows, 16B aligned)
#define FPI 65           // f32 pitch for logits
#define ATT_SMEM 46080

// ---------------------------------------------------------------------------
// Local attention: one block per (b, seg, h). mma.sync everywhere.
// ---------------------------------------------------------------------------
__global__ __launch_bounds__(256, 3) void attn_local_k()
{
    extern __shared__ char smraw[];
    __half* qh = (__half*)smraw;
    __half* kh = (__half*)(smraw + 9216);
    float*  lg = (float*)smraw;
    __half* vh = (__half*)(smraw + 18432);
    __half* ph = (__half*)(smraw + 27648);
    __half* mh = (__half*)(smraw + 36864);

    const __half* gq = g_qkvh;
    const __half* gk = g_qkvh + (size_t)NTOK * DMODEL;
    const __half* gv = g_qkvh + 2 * (size_t)NTOK * DMODEL;

    int bid = blockIdx.x;
    int h   = bid % NH;
    int seg = (bid / NH) % NSEG;
    int b   = bid / (NH * NSEG);
    int t0  = b * SLEN + seg * SEGLEN;
    int tid = threadIdx.x;
    const int wid = tid >> 5, lane = tid & 31;
    const int wm = wid >> 1, wn = wid & 1;

    for (int i = tid; i < 512; i += 256) {
        int r = i >> 3, c = (i & 7) * 8;
        size_t g = (size_t)(t0 + r) * DMODEL + h * DH + c;
        *(uint4*)&qh[r * HPI + c] = *(const uint4*)&gq[g];
        *(uint4*)&kh[r * HPI + c] = *(const uint4*)&gk[g];
        *(uint4*)&vh[r * HPI + c] = *(const uint4*)&gv[g];
    }
    __syncthreads();

    const int a_row = lane & 15, a_kh = (lane >> 4) * 8;
    const int b_row = (lane & 7) + ((lane >> 4) << 3), b_kh = ((lane >> 3) & 1) * 8;

    // P1: logits = Q @ K^T
    float lc[4][4];
    #pragma unroll
    for (int nt = 0; nt < 4; nt++)
        #pragma unroll
        for (int t = 0; t < 4; t++) lc[nt][t] = 0.0f;
    #pragma unroll
    for (int ks = 0; ks < 4; ks++) {
        uint32_t aa[4], bbf[4][2];
        LDSM4(aa[0], aa[1], aa[2], aa[3],
              smem_u32(&qh[(wm * 16 + a_row) * HPI + ks * 16 + a_kh]));
        #pragma unroll
        for (int j = 0; j < 2; j++)
            LDSM4(bbf[2*j][0], bbf[2*j][1], bbf[2*j+1][0], bbf[2*j+1][1],
                  smem_u32(&kh[(wn * 32 + j * 16 + b_row) * HPI + ks * 16 + b_kh]));
        #pragma unroll
        for (int nt = 0; nt < 4; nt++)
            MMA16816(lc[nt][0], lc[nt][1], lc[nt][2], lc[nt][3],
                     aa[0], aa[1], aa[2], aa[3], bbf[nt][0], bbf[nt][1]);
    }
    __syncthreads();

    {
        int crow = wm * 16 + (lane >> 2);
        int ccol = wn * 32 + (lane & 3) * 2;
        #pragma unroll
        for (int nt = 0; nt < 4; nt++) {
            lg[crow * FPI + ccol + nt * 8]           = lc[nt][0];
            lg[crow * FPI + ccol + nt * 8 + 1]       = lc[nt][1];
            lg[(crow + 8) * FPI + ccol + nt * 8]     = lc[nt][2];
            lg[(crow + 8) * FPI + ccol + nt * 8 + 1] = lc[nt][3];
        }
    }
    __syncthreads();

    // P2: dual softmax
    for (int r = wid; r < 64; r += 8) {
        float l0 = lg[r * FPI + lane];
        float l1 = lg[r * FPI + 32 + lane];
        float mx = warp_max(fmaxf(l0, l1));
        float k0 = (lane <= r)      ? l0 : -3e38f;
        float k1 = (lane + 32 <= r) ? l1 : -3e38f;
        float mm = warp_max(fmaxf(k0, k1));
        float e0 = __expf(l0 - mx), e1 = __expf(l1 - mx);
        float su = warp_sum(e0 + e1);
        float em0 = (lane <= r)      ? __expf(l0 - mm) : 0.0f;
        float em1 = (lane + 32 <= r) ? __expf(l1 - mm) : 0.0f;
        float ss = warp_sum(em0 + em1);
        float inv = 1.0f / su;
        ph[r * HPI + lane]      = __float2half(e0 * inv);
        ph[r * HPI + 32 + lane] = __float2half(e1 * inv);
        mh[r * HPI + lane]      = __float2half(em0);
        mh[r * HPI + 32 + lane] = __float2half(em1);
        if (lane == 0) {
            g_mloc[(t0 + r) * NH + h] = mm;
            g_sloc[(t0 + r) * NH + h] = ss;
        }
    }
    __syncthreads();

    // P3: ra = P @ V, la = Pm @ V
    float a1[4][4], a2[4][4];
    #pragma unroll
    for (int nt = 0; nt < 4; nt++)
        #pragma unroll
        for (int t = 0; t < 4; t++) { a1[nt][t] = 0.0f; a2[nt][t] = 0.0f; }
    #pragma unroll
    for (int ks = 0; ks < 4; ks++) {
        uint32_t pa[4], ma[4], vb[4][2];
        LDSM4(pa[0], pa[1], pa[2], pa[3],
              smem_u32(&ph[(wm * 16 + a_row) * HPI + ks * 16 + a_kh]));
        LDSM4(ma[0], ma[1], ma[2], ma[3],
              smem_u32(&mh[(wm * 16 + a_row) * HPI + ks * 16 + a_kh]));
        #pragma unroll
        for (int j = 0; j < 2; j++)
            LDSM4T(vb[2*j][0], vb[2*j][1], vb[2*j+1][0], vb[2*j+1][1],
                   smem_u32(&vh[(ks * 16 + (lane & 15)) * HPI
                                + wn * 32 + j * 16 + (lane >> 4) * 8]));
        #pragma unroll
        for (int nt = 0; nt < 4; nt++) {
            MMA16816(a1[nt][0], a1[nt][1], a1[nt][2], a1[nt][3],
                     pa[0], pa[1], pa[2], pa[3], vb[nt][0], vb[nt][1]);
            MMA16816(a2[nt][0], a2[nt][1], a2[nt][2], a2[nt][3],
                     ma[0], ma[1], ma[2], ma[3], vb[nt][0], vb[nt][1]);
        }
    }

    // P4: epilogue (ra fp16, la fp16)
    {
        int orow = wm * 16 + (lane >> 2);
        #pragma unroll
        for (int nt = 0; nt < 4; nt++) {
            int col = wn * 32 + nt * 8 + (lane & 3) * 2;
            #pragma unroll
            for (int hh = 0; hh < 2; hh++) {
                int rr = orow + hh * 8;
                size_t base = (size_t)(t0 + rr) * DMODEL + h * DH + col;
                *(__half2*)&g_rah[base] = __floats2half2_rn(a1[nt][hh*2], a1[nt][hh*2+1]);
                *(__half2*)&g_lah[base] = __floats2half2_rn(a2[nt][hh*2], a2[nt][hh*2+1]);
            }
        }
    }
}

// ---------------------------------------------------------------------------
// Global attention + merge: one block per (b, l, h). mma.sync everywhere.
// ---------------------------------------------------------------------------
__global__ __launch_bounds__(256, 3) void attn_global_k()
{
    extern __shared__ char smraw[];
    __half* qh = (__half*)smraw;
    __half* kh = (__half*)(smraw + 9216);
    float*  lg = (float*)smraw;
    __half* rh = (__half*)(smraw + 18432);
    __half* ph = (__half*)(smraw + 27648);
    __shared__ float s_cl[64], s_cg[64];

    const __half* gq = g_qkvh;

    int bid = blockIdx.x;
    int h   = bid % NH;
    int l   = (bid / NH) % SEGLEN;
    int b   = bid / (NH * SEGLEN);
    int tid = threadIdx.x;
    const int wid = tid >> 5, lane = tid & 31;
    const int wm = wid >> 1, wn = wid & 1;

    for (int i = tid; i < 512; i += 256) {
        int r = i >> 3, c = (i & 7) * 8;
        size_t g = (size_t)(b * SLEN + r * SEGLEN + l) * DMODEL + h * DH + c;
        *(uint4*)&qh[r * HPI + c] = *(const uint4*)&gq[g];
        *(uint4*)&kh[r * HPI + c] = *(const uint4*)&g_k2h[g];
        *(uint4*)&rh[r * HPI + c] = *(const uint4*)&g_rah[g];
    }
    __syncthreads();

    const int a_row = lane & 15, a_kh = (lane >> 4) * 8;
    const int b_row = (lane & 7) + ((lane >> 4) << 3), b_kh = ((lane >> 3) & 1) * 8;

    // P1: logits = Q @ K2^T
    float lc[4][4];
    #pragma unroll
    for (int nt = 0; nt < 4; nt++)
        #pragma unroll
        for (int t = 0; t < 4; t++) lc[nt][t] = 0.0f;
    #pragma unroll
    for (int ks = 0; ks < 4; ks++) {
        uint32_t aa[4], bbf[4][2];
        LDSM4(aa[0], aa[1], aa[2], aa[3],
              smem_u32(&qh[(wm * 16 + a_row) * HPI + ks * 16 + a_kh]));
        #pragma unroll
        for (int j = 0; j < 2; j++)
            LDSM4(bbf[2*j][0], bbf[2*j][1], bbf[2*j+1][0], bbf[2*j+1][1],
                  smem_u32(&kh[(wn * 32 + j * 16 + b_row) * HPI + ks * 16 + b_kh]));
        #pragma unroll
        for (int nt = 0; nt < 4; nt++)
            MMA16816(lc[nt][0], lc[nt][1], lc[nt][2], lc[nt][3],
                     aa[0], aa[1], aa[2], aa[3], bbf[nt][0], bbf[nt][1]);
    }
    __syncthreads();

    {
        int crow = wm * 16 + (lane >> 2);
        int ccol = wn * 32 + (lane & 3) * 2;
        #pragma unroll
        for (int nt = 0; nt < 4; nt++) {
            int c0c = ccol + nt * 8;
            lg[crow * FPI + c0c]           = lc[nt][0] + ((c0c     >= crow)     ? NEGINF : 0.0f);
            lg[crow * FPI + c0c + 1]       = lc[nt][1] + ((c0c + 1 >= crow)     ? NEGINF : 0.0f);
            lg[(crow + 8) * FPI + c0c]     = lc[nt][2] + ((c0c     >= crow + 8) ? NEGINF : 0.0f);
            lg[(crow + 8) * FPI + c0c + 1] = lc[nt][3] + ((c0c + 1 >= crow + 8) ? NEGINF : 0.0f);
        }
    }
    __syncthreads();

    // P2: softmax stats + merge coefficients
    for (int r = wid; r < 64; r += 8) {
        float l0 = lg[r * FPI + lane];
        float l1 = lg[r * FPI + 32 + lane];
        float mg = warp_max(fmaxf(l0, l1));
        float e0 = __expf(l0 - mg), e1 = __expf(l1 - mg);
        float sg = warp_sum(e0 + e1);
        ph[r * HPI + lane]      = __float2half(e0);
        ph[r * HPI + 32 + lane] = __float2half(e1);
        if (lane == 0) {
            int t = b * SLEN + r * SEGLEN + l;
            float mlc = g_mloc[t * NH + h];
            float slc = g_sloc[t * NH + h];
            float m  = fmaxf(mlc, mg);
            float al = __expf(mlc - m);
            float ag = __expf(mg - m);
            float inv = 1.0f / (slc * al + sg * ag);
            s_cl[r] = al * inv;
            s_cg[r] = ag * inv;
        }
    }
    __syncthreads();

    // P3: ga = Pg @ RA
    float ga[4][4];
    #pragma unroll
    for (int nt = 0; nt < 4; nt++)
        #pragma unroll
        for (int t = 0; t < 4; t++) ga[nt][t] = 0.0f;
    #pragma unroll
    for (int ks = 0; ks < 4; ks++) {
        uint32_t pa[4], vb[4][2];
        LDSM4(pa[0], pa[1], pa[2], pa[3],
              smem_u32(&ph[(wm * 16 + a_row) * HPI + ks * 16 + a_kh]));
        #pragma unroll
        for (int j = 0; j < 2; j++)
            LDSM4T(vb[2*j][0], vb[2*j][1], vb[2*j+1][0], vb[2*j+1][1],
                   smem_u32(&rh[(ks * 16 + (lane & 15)) * HPI
                                + wn * 32 + j * 16 + (lane >> 4) * 8]));
        #pragma unroll
        for (int nt = 0; nt < 4; nt++)
            MMA16816(ga[nt][0], ga[nt][1], ga[nt][2], ga[nt][3],
                     pa[0], pa[1], pa[2], pa[3], vb[nt][0], vb[nt][1]);
    }

    // P4: merge with local branch
    {
        int orow = wm * 16 + (lane >> 2);
        #pragma unroll
        for (int nt = 0; nt < 4; nt++) {
            int col = wn * 32 + nt * 8 + (lane & 3) * 2;
            #pragma unroll
            for (int hh = 0; hh < 2; hh++) {
                int rr = orow + hh * 8;
                size_t base = (size_t)(b * SLEN + rr * SEGLEN + l) * DMODEL + h * DH + col;
                float2 la = __half22float2(*(__half2*)&g_lah[base]);
                float cl = s_cl[rr], cg = s_cg[rr];
                float ox = cl * la.x + cg * ga[nt][hh*2];
                float oy = cl * la.y + cg * ga[nt][hh*2+1];
                *(__half2*)&g_ah[base] = __floats2half2_rn(ox, oy);
            }
        }
    }
}

// ---------------------------------------------------------------------------
// LayerNorm: reads kt f32, writes normalized result as fp16
// ---------------------------------------------------------------------------
__global__ __launch_bounds__(256) void ln_k(const float* __restrict__ x,
                                            const float* __restrict__ sc,
                                            const float* __restrict__ bs,
                                            __half* __restrict__ oh)
{
    size_t row = blockIdx.x;
    const float* p = x + row * DMODEL;
    int c = threadIdx.x * 4;
    float4 v = *(const float4*)(p + c);
    float s  = v.x + v.y + v.z + v.w;
    float sq = v.x * v.x + v.y * v.y + v.z * v.z + v.w * v.w;
    s  = warp_sum(s);
    sq = warp_sum(sq);
    __shared__ float rs[8], rq[8];
    int warp = threadIdx.x >> 5, lane = threadIdx.x & 31;
    if (lane == 0) { rs[warp] = s; rq[warp] = sq; }
    __syncthreads();
    if (warp == 0) {
        float a = (lane < 8) ? rs[lane] : 0.0f;
        float b = (lane < 8) ? rq[lane] : 0.0f;
        a = warp_sum(a);
        b = warp_sum(b);
        if (lane == 0) { rs[0] = a; rq[0] = b; }
    }
    __syncthreads();
    float mean = rs[0] * (1.0f / DMODEL);
    float var  = rq[0] * (1.0f / DMODEL) - mean * mean;
    float inv  = rsqrtf(var + 1e-6f);
    float4 g = *(const float4*)(sc + c);
    float4 b4 = *(const float4*)(bs + c);
    v.x = (v.x - mean) * inv * g.x + b4.x;
    v.y = (v.y - mean) * inv * g.y + b4.y;
    v.z = (v.z - mean) * inv * g.z + b4.z;
    v.w = (v.w - mean) * inv * g.w + b4.w;
    size_t o = row * DMODEL + c;
    *(uint2*)(oh + o) = make_uint2(hb(v.x) | (hb(v.y) << 16),
                                   hb(v.z) | (hb(v.w) << 16));
}

// ---------------------------------------------------------------------------
// Host launcher
// ---------------------------------------------------------------------------
extern "C" void kernel_launch(void* const* d_in, const int* in_sizes, int n_in,
                              void* d_out, int out_size)
{
    const float* x    = (const float*)d_in[0];
    const float* Wq   = (const float*)d_in[1];
    const float* Wk   = (const float*)d_in[2];
    const float* Wv   = (const float*)d_in[3];
    const float* Wrow = (const float*)d_in[4];
    const float* lns  = (const float*)d_in[5];
    const float* lnb  = (const float*)d_in[6];
    const float* Wk2  = (const float*)d_in[7];
    const float* Wout = (const float*)d_in[8];
    float* out = (float*)d_out;

    float *kt;
    cudaGetSymbolAddress((void**)&kt, g_kt);

    __half *w16, *ah, *rah, *qkvh, *k2h;
    cudaGetSymbolAddress((void**)&w16,  g_w16);
    cudaGetSymbolAddress((void**)&ah,   g_ah);
    cudaGetSymbolAddress((void**)&rah,  g_rah);
    cudaGetSymbolAddress((void**)&qkvh, g_qkvh);
    cudaGetSymbolAddress((void**)&k2h,  g_k2h);
    const size_t MSZ = (size_t)NTOK * DMODEL;
    const size_t WSZ = (size_t)DMODEL * DMODEL;

    cudaFuncSetAttribute(attn_local_k,  cudaFuncAttributeMaxDynamicSharedMemorySize, ATT_SMEM);
    cudaFuncSetAttribute(attn_global_k, cudaFuncAttributeMaxDynamicSharedMemorySize, ATT_SMEM);
    cudaFuncSetAttribute(gemm_mma<true>,  cudaFuncAttributeMaxDynamicSharedMemorySize, GSMEM);
    cudaFuncSetAttribute(gemm_mma<false>, cudaFuncAttributeMaxDynamicSharedMemorySize, GSMEM);

    // weight prep (transpose + fp16; Wq pre-scaled by 1/sqrt(HD)=0.125)
    dim3 wsg(32, 32), wst(256);
    wprep_k<<<wsg, wst>>>(Wq,   w16 + 0 * WSZ, 0.125f);
    wprep_k<<<wsg, wst>>>(Wk,   w16 + 1 * WSZ, 1.0f);
    wprep_k<<<wsg, wst>>>(Wv,   w16 + 2 * WSZ, 1.0f);
    wprep_k<<<wsg, wst>>>(Wrow, w16 + 3 * WSZ, 1.0f);
    wprep_k<<<wsg, wst>>>(Wk2,  w16 + 4 * WSZ, 1.0f);
    wprep_k<<<wsg, wst>>>(Wout, w16 + 5 * WSZ, 1.0f);

    dim3 bt(256);
    const int ACONV_G = (NTOK * DMODEL) / (256 * 4);

    // x -> fp16, then fused QKV projection (fp16 out), persistent grid
    aconv_k<<<ACONV_G, 256>>>(x, ah);
    gemm_mma<true><<<GGRID, bt, GSMEM>>>(ah, w16, nullptr, qkvh, MSZ, 24, 3072);

    // local attention (tensor-core)
    attn_local_k<<<NBATCH * NSEG * NH, 256, ATT_SMEM>>>();

    // key_row = ra @ Wrow + x (f32) ; LN -> fp16 ; @ Wk2 (fp16 out)
    gemm_mma<false><<<GGRID, bt, GSMEM>>>(rah, w16 + 3 * WSZ, x, kt, 0, 8, 1024);
    ln_k<<<NTOK, 256>>>(kt, lns, lnb, ah);
    gemm_mma<true><<<GGRID, bt, GSMEM>>>(ah, w16 + 4 * WSZ, nullptr, k2h, 0, 8, 1024);

    // global attention + merge (tensor-core)
    attn_global_k<<<NBATCH * SEGLEN * NH, 256, ATT_SMEM>>>();

    // output projection (f32 out)
    gemm_mma<false><<<GGRID, bt, GSMEM>>>(ah, w16 + 5 * WSZ, nullptr, out, 0, 8, 1024);
}

// round 13
// speedup vs baseline: 1.2037x; 1.2037x over previous
#include <cuda_runtime.h>
#include <cuda_fp16.h>
#include <cstdint>

// ---------------------------------------------------------------------------
// Problem constants
// ---------------------------------------------------------------------------
#define NTOK   16384      // B*S
#define DMODEL 1024
#define NH     16
#define DH     64
#define SEGLEN 64
#define NSEG   64
#define SLEN   4096
#define NBATCH 4
#define NEGINF -1e10f
#define GGRID  296        // persistent GEMM grid (2 per SM)

// ---------------------------------------------------------------------------
// Scratch (device globals)
// ---------------------------------------------------------------------------
__device__ __half g_qkvh[3 * NTOK * DMODEL];  // q | k | v fp16
__device__ __half g_rah [NTOK * DMODEL];      // row_attn fp16
__device__ __half g_k2h [NTOK * DMODEL];      // key_row2 fp16
__device__ __half g_ah  [NTOK * DMODEL];      // generic fp16 activation
__device__ __half g_lah [NTOK * DMODEL];      // unnormalized masked-local P@V (fp16)
__device__ float  g_kt  [NTOK * DMODEL];      // key_row f32 (pre-LN)
__device__ float  g_mloc[NTOK * NH];
__device__ float  g_sloc[NTOK * NH];

// Pre-transposed fp16 weights: [6][N=1024][K=1024] (Wq pre-scaled by 0.125)
__device__ __half g_w16[6][DMODEL * DMODEL];

// ---------------------------------------------------------------------------
// Helpers
// ---------------------------------------------------------------------------
__device__ __forceinline__ uint32_t smem_u32(const void* p) {
    uint32_t a;
    asm("{ .reg .u64 t; cvta.to.shared.u64 t, %1; cvt.u32.u64 %0, t; }"
        : "=r"(a) : "l"(p));
    return a;
}
__device__ __forceinline__ void cpasync16(uint32_t s, const void* g) {
    asm volatile("cp.async.cg.shared.global [%0], [%1], 16;" :: "r"(s), "l"(g));
}
#define CP_COMMIT() asm volatile("cp.async.commit_group;")
#define CP_WAIT1()  asm volatile("cp.async.wait_group 1;")
#define CP_WAIT0()  asm volatile("cp.async.wait_group 0;")

#define LDSM4(r0, r1, r2, r3, addr) \
    asm volatile("ldmatrix.sync.aligned.m8n8.x4.shared.b16 {%0,%1,%2,%3}, [%4];" \
                 : "=r"(r0), "=r"(r1), "=r"(r2), "=r"(r3) : "r"(addr))
#define LDSM4T(r0, r1, r2, r3, addr) \
    asm volatile("ldmatrix.sync.aligned.m8n8.x4.trans.shared.b16 {%0,%1,%2,%3}, [%4];" \
                 : "=r"(r0), "=r"(r1), "=r"(r2), "=r"(r3) : "r"(addr))

#define MMA16816(c0, c1, c2, c3, a0, a1, a2, a3, b0, b1) \
    asm volatile("mma.sync.aligned.m16n8k16.row.col.f32.f16.f16.f32 " \
                 "{%0,%1,%2,%3}, {%4,%5,%6,%7}, {%8,%9}, {%0,%1,%2,%3};" \
                 : "+f"(c0), "+f"(c1), "+f"(c2), "+f"(c3) \
                 : "r"(a0), "r"(a1), "r"(a2), "r"(a3), "r"(b0), "r"(b1))

__device__ __forceinline__ uint32_t hb(float v) {
    return (uint32_t)__half_as_ushort(__float2half(v));
}

// ---------------------------------------------------------------------------
// Weight transpose + fp16 convert, all 6 weights in one launch (grid.z = 6).
//   W[K][N] -> T[N][K] fp16 ; weight 0 (Wq) pre-scaled by 0.125
// ---------------------------------------------------------------------------
struct W6 { const float* p[6]; };

__global__ __launch_bounds__(256) void wprep_all(W6 w, __half* __restrict__ T)
{
    __shared__ float t[32][33];
    int wi = blockIdx.z;
    const float* W = w.p[wi];
    __half* Tw = T + (size_t)wi * DMODEL * DMODEL;
    float scale = (wi == 0) ? 0.125f : 1.0f;
    int bn = blockIdx.x * 32;
    int bk = blockIdx.y * 32;
    int x = threadIdx.x & 31;
    int y = threadIdx.x >> 5;
    #pragma unroll
    for (int i = 0; i < 32; i += 8)
        t[y + i][x] = W[(size_t)(bk + y + i) * DMODEL + bn + x];
    __syncthreads();
    #pragma unroll
    for (int i = 0; i < 32; i += 8) {
        float v = t[x][y + i] * scale;
        Tw[(size_t)(bn + y + i) * DMODEL + bk + x] = __float2half(v);
    }
}

// ---------------------------------------------------------------------------
// Activation fp32 -> fp16 convert (only used for the input x)
// ---------------------------------------------------------------------------
__global__ __launch_bounds__(256) void aconv_k(const float* __restrict__ in,
                                               __half* __restrict__ oh)
{
    size_t i = ((size_t)blockIdx.x * 256 + threadIdx.x) * 4;
    float4 v = *(const float4*)(in + i);
    *(uint2*)(oh + i) = make_uint2(hb(v.x) | (hb(v.y) << 16),
                                   hb(v.z) | (hb(v.w) << 16));
}

// ---------------------------------------------------------------------------
// Persistent tensor-core GEMM (pure fp16, fp32 accumulate).  BK=32.
//   tN = t % tilesX, tM = t / tilesX.
// ---------------------------------------------------------------------------
#define GBK    32
#define GPITCH 40                      // fp16 elements per smem row (80 B)
#define GTILE_B (128 * GPITCH * 2)     // 10240 B per tile
#define GSTAGE_B (2 * GTILE_B)         // A, B = 20480 B
#define GSMEM   (3 * GSTAGE_B)         // 3 stages = 61440 B

template<bool HALF_OUT>
__global__ __launch_bounds__(256) void gemm_mma(
    const __half* __restrict__ Ah,
    const __half* __restrict__ Bf,
    const float* __restrict__ res, void* __restrict__ Cv, size_t matStride,
    int tilesX, int tilesTotal)
{
    extern __shared__ char dsm[];
    const uint32_t sb = smem_u32(dsm);

    const int tid  = threadIdx.x;
    const int wid  = tid >> 5;
    const int lane = tid & 31;
    const int wm = wid & 1;
    const int wn = wid >> 1;
    const int r0 = tid >> 2;
    const int c0 = (tid & 3);
    const int a_row = (lane & 15);
    const int a_kh  = (lane >> 4) * 8;
    const int b_row = (lane & 7) + ((lane >> 4) << 3);
    const int b_kh  = ((lane >> 3) & 1) * 8;

    for (int t = blockIdx.x; t < tilesTotal; t += gridDim.x) {
        const int tN = t % tilesX, tM = t / tilesX;
        const __half* Ahp = Ah + (size_t)(tM * 128) * DMODEL;
        const __half* Bp  = Bf + (size_t)(tN * 128) * DMODEL;

        float acc[4][4][4];
        #pragma unroll
        for (int i = 0; i < 4; i++)
            #pragma unroll
            for (int j = 0; j < 4; j++)
                #pragma unroll
                for (int tt = 0; tt < 4; tt++) acc[i][j][tt] = 0.0f;

        auto issue_chunk = [&](int c, int st) {
            const int k0 = c * GBK;
            uint32_t s = sb + st * GSTAGE_B;
            #pragma unroll
            for (int half = 0; half < 2; half++) {
                int r = r0 + half * 64;
                uint32_t so = (uint32_t)(r * (GPITCH * 2) + c0 * 16);
                size_t go = (size_t)r * DMODEL + (k0 + c0 * 8);
                cpasync16(s + 0 * GTILE_B + so, Ahp + go);
                cpasync16(s + 1 * GTILE_B + so, Bp  + go);
            }
            CP_COMMIT();
        };

        issue_chunk(0, 0);
        issue_chunk(1, 1);

        const int NC = DMODEL / GBK;   // 32
        for (int c = 0; c < NC; c++) {
            const int st = c % 3;
            if (c + 1 < NC) CP_WAIT1(); else CP_WAIT0();
            __syncthreads();
            if (c + 2 < NC) issue_chunk(c + 2, (c + 2) % 3);

            uint32_t sA = sb + st * GSTAGE_B;
            uint32_t sB = sA + GTILE_B;

            #pragma unroll
            for (int ks = 0; ks < 2; ks++) {
                const int kb = ks * 16;
                uint32_t aa[4][4], bbr[4][2];
                #pragma unroll
                for (int mt = 0; mt < 4; mt++) {
                    uint32_t off = (uint32_t)((wm * 64 + mt * 16 + a_row) * (GPITCH * 2)
                                              + (kb + a_kh) * 2);
                    LDSM4(aa[mt][0], aa[mt][1], aa[mt][2], aa[mt][3], sA + off);
                }
                #pragma unroll
                for (int j = 0; j < 2; j++) {
                    uint32_t off = (uint32_t)((wn * 32 + j * 16 + b_row) * (GPITCH * 2)
                                              + (kb + b_kh) * 2);
                    LDSM4(bbr[2*j][0], bbr[2*j][1], bbr[2*j+1][0], bbr[2*j+1][1], sB + off);
                }
                #pragma unroll
                for (int mt = 0; mt < 4; mt++)
                    #pragma unroll
                    for (int nt = 0; nt < 4; nt++)
                        MMA16816(acc[mt][nt][0], acc[mt][nt][1], acc[mt][nt][2], acc[mt][nt][3],
                                 aa[mt][0], aa[mt][1], aa[mt][2], aa[mt][3],
                                 bbr[nt][0], bbr[nt][1]);
            }
        }

        // Epilogue
        const int colb = (tN & 7) * 128;
        #pragma unroll
        for (int mt = 0; mt < 4; mt++) {
            #pragma unroll
            for (int nt = 0; nt < 4; nt++) {
                int row = tM * 128 + wm * 64 + mt * 16 + (lane >> 2);
                int col = colb + wn * 32 + nt * 8 + (lane & 3) * 2;
                #pragma unroll
                for (int hh = 0; hh < 2; hh++) {
                    size_t o = (size_t)(row + hh * 8) * DMODEL + col;
                    float vx = acc[mt][nt][hh * 2 + 0];
                    float vy = acc[mt][nt][hh * 2 + 1];
                    if (HALF_OUT) {
                        __half* Cb = (__half*)Cv + (size_t)(tN >> 3) * matStride;
                        *(__half2*)(Cb + o) = __floats2half2_rn(vx, vy);
                    } else {
                        float* Cb = (float*)Cv + (size_t)(tN >> 3) * matStride;
                        if (res) {
                            float2 rr = *(const float2*)(res + o);
                            vx += rr.x; vy += rr.y;
                        }
                        *(float2*)(Cb + o) = make_float2(vx, vy);
                    }
                }
            }
        }
        __syncthreads();   // guard smem reuse by next tile
    }
}

// ---------------------------------------------------------------------------
// Warp utils
// ---------------------------------------------------------------------------
__device__ __forceinline__ float warp_max(float v) {
    #pragma unroll
    for (int o = 16; o > 0; o >>= 1) v = fmaxf(v, __shfl_xor_sync(0xffffffffu, v, o));
    return v;
}
__device__ __forceinline__ float warp_sum(float v) {
    #pragma unroll
    for (int o = 16; o > 0; o >>= 1) v += __shfl_xor_sync(0xffffffffu, v, o);
    return v;
}

// ---------------------------------------------------------------------------
// Attention smem layout (dynamic, 46080 B)
// ---------------------------------------------------------------------------
#define HPI 72           // half pitch (144 B rows, 16B aligned)
#define FPI 65           // f32 pitch for logits
#define ATT_SMEM 46080

// ---------------------------------------------------------------------------
// Local attention: one block per (b, seg, h). mma.sync everywhere.
// ---------------------------------------------------------------------------
__global__ __launch_bounds__(256, 3) void attn_local_k()
{
    extern __shared__ char smraw[];
    __half* qh = (__half*)smraw;
    __half* kh = (__half*)(smraw + 9216);
    float*  lg = (float*)smraw;
    __half* vh = (__half*)(smraw + 18432);
    __half* ph = (__half*)(smraw + 27648);
    __half* mh = (__half*)(smraw + 36864);

    const __half* gq = g_qkvh;
    const __half* gk = g_qkvh + (size_t)NTOK * DMODEL;
    const __half* gv = g_qkvh + 2 * (size_t)NTOK * DMODEL;

    int bid = blockIdx.x;
    int h   = bid % NH;
    int seg = (bid / NH) % NSEG;
    int b   = bid / (NH * NSEG);
    int t0  = b * SLEN + seg * SEGLEN;
    int tid = threadIdx.x;
    const int wid = tid >> 5, lane = tid & 31;
    const int wm = wid >> 1, wn = wid & 1;

    for (int i = tid; i < 512; i += 256) {
        int r = i >> 3, c = (i & 7) * 8;
        size_t g = (size_t)(t0 + r) * DMODEL + h * DH + c;
        *(uint4*)&qh[r * HPI + c] = *(const uint4*)&gq[g];
        *(uint4*)&kh[r * HPI + c] = *(const uint4*)&gk[g];
        *(uint4*)&vh[r * HPI + c] = *(const uint4*)&gv[g];
    }
    __syncthreads();

    const int a_row = lane & 15, a_kh = (lane >> 4) * 8;
    const int b_row = (lane & 7) + ((lane >> 4) << 3), b_kh = ((lane >> 3) & 1) * 8;

    // P1: logits = Q @ K^T
    float lc[4][4];
    #pragma unroll
    for (int nt = 0; nt < 4; nt++)
        #pragma unroll
        for (int t = 0; t < 4; t++) lc[nt][t] = 0.0f;
    #pragma unroll
    for (int ks = 0; ks < 4; ks++) {
        uint32_t aa[4], bbf[4][2];
        LDSM4(aa[0], aa[1], aa[2], aa[3],
              smem_u32(&qh[(wm * 16 + a_row) * HPI + ks * 16 + a_kh]));
        #pragma unroll
        for (int j = 0; j < 2; j++)
            LDSM4(bbf[2*j][0], bbf[2*j][1], bbf[2*j+1][0], bbf[2*j+1][1],
                  smem_u32(&kh[(wn * 32 + j * 16 + b_row) * HPI + ks * 16 + b_kh]));
        #pragma unroll
        for (int nt = 0; nt < 4; nt++)
            MMA16816(lc[nt][0], lc[nt][1], lc[nt][2], lc[nt][3],
                     aa[0], aa[1], aa[2], aa[3], bbf[nt][0], bbf[nt][1]);
    }
    __syncthreads();

    {
        int crow = wm * 16 + (lane >> 2);
        int ccol = wn * 32 + (lane & 3) * 2;
        #pragma unroll
        for (int nt = 0; nt < 4; nt++) {
            lg[crow * FPI + ccol + nt * 8]           = lc[nt][0];
            lg[crow * FPI + ccol + nt * 8 + 1]       = lc[nt][1];
            lg[(crow + 8) * FPI + ccol + nt * 8]     = lc[nt][2];
            lg[(crow + 8) * FPI + ccol + nt * 8 + 1] = lc[nt][3];
        }
    }
    __syncthreads();

    // P2: dual softmax
    for (int r = wid; r < 64; r += 8) {
        float l0 = lg[r * FPI + lane];
        float l1 = lg[r * FPI + 32 + lane];
        float mx = warp_max(fmaxf(l0, l1));
        float k0 = (lane <= r)      ? l0 : -3e38f;
        float k1 = (lane + 32 <= r) ? l1 : -3e38f;
        float mm = warp_max(fmaxf(k0, k1));
        float e0 = __expf(l0 - mx), e1 = __expf(l1 - mx);
        float su = warp_sum(e0 + e1);
        float em0 = (lane <= r)      ? __expf(l0 - mm) : 0.0f;
        float em1 = (lane + 32 <= r) ? __expf(l1 - mm) : 0.0f;
        float ss = warp_sum(em0 + em1);
        float inv = 1.0f / su;
        ph[r * HPI + lane]      = __float2half(e0 * inv);
        ph[r * HPI + 32 + lane] = __float2half(e1 * inv);
        mh[r * HPI + lane]      = __float2half(em0);
        mh[r * HPI + 32 + lane] = __float2half(em1);
        if (lane == 0) {
            g_mloc[(t0 + r) * NH + h] = mm;
            g_sloc[(t0 + r) * NH + h] = ss;
        }
    }
    __syncthreads();

    // P3: ra = P @ V, la = Pm @ V
    float a1[4][4], a2[4][4];
    #pragma unroll
    for (int nt = 0; nt < 4; nt++)
        #pragma unroll
        for (int t = 0; t < 4; t++) { a1[nt][t] = 0.0f; a2[nt][t] = 0.0f; }
    #pragma unroll
    for (int ks = 0; ks < 4; ks++) {
        uint32_t pa[4], ma[4], vb[4][2];
        LDSM4(pa[0], pa[1], pa[2], pa[3],
              smem_u32(&ph[(wm * 16 + a_row) * HPI + ks * 16 + a_kh]));
        LDSM4(ma[0], ma[1], ma[2], ma[3],
              smem_u32(&mh[(wm * 16 + a_row) * HPI + ks * 16 + a_kh]));
        #pragma unroll
        for (int j = 0; j < 2; j++)
            LDSM4T(vb[2*j][0], vb[2*j][1], vb[2*j+1][0], vb[2*j+1][1],
                   smem_u32(&vh[(ks * 16 + (lane & 15)) * HPI
                                + wn * 32 + j * 16 + (lane >> 4) * 8]));
        #pragma unroll
        for (int nt = 0; nt < 4; nt++) {
            MMA16816(a1[nt][0], a1[nt][1], a1[nt][2], a1[nt][3],
                     pa[0], pa[1], pa[2], pa[3], vb[nt][0], vb[nt][1]);
            MMA16816(a2[nt][0], a2[nt][1], a2[nt][2], a2[nt][3],
                     ma[0], ma[1], ma[2], ma[3], vb[nt][0], vb[nt][1]);
        }
    }

    // P4: epilogue (ra fp16, la fp16)
    {
        int orow = wm * 16 + (lane >> 2);
        #pragma unroll
        for (int nt = 0; nt < 4; nt++) {
            int col = wn * 32 + nt * 8 + (lane & 3) * 2;
            #pragma unroll
            for (int hh = 0; hh < 2; hh++) {
                int rr = orow + hh * 8;
                size_t base = (size_t)(t0 + rr) * DMODEL + h * DH + col;
                *(__half2*)&g_rah[base] = __floats2half2_rn(a1[nt][hh*2], a1[nt][hh*2+1]);
                *(__half2*)&g_lah[base] = __floats2half2_rn(a2[nt][hh*2], a2[nt][hh*2+1]);
            }
        }
    }
}

// ---------------------------------------------------------------------------
// Global attention + merge: one block per (b, l, h). mma.sync everywhere.
// ---------------------------------------------------------------------------
__global__ __launch_bounds__(256, 3) void attn_global_k()
{
    extern __shared__ char smraw[];
    __half* qh = (__half*)smraw;
    __half* kh = (__half*)(smraw + 9216);
    float*  lg = (float*)smraw;
    __half* rh = (__half*)(smraw + 18432);
    __half* ph = (__half*)(smraw + 27648);
    __shared__ float s_cl[64], s_cg[64];

    const __half* gq = g_qkvh;

    int bid = blockIdx.x;
    int h   = bid % NH;
    int l   = (bid / NH) % SEGLEN;
    int b   = bid / (NH * SEGLEN);
    int tid = threadIdx.x;
    const int wid = tid >> 5, lane = tid & 31;
    const int wm = wid >> 1, wn = wid & 1;

    for (int i = tid; i < 512; i += 256) {
        int r = i >> 3, c = (i & 7) * 8;
        size_t g = (size_t)(b * SLEN + r * SEGLEN + l) * DMODEL + h * DH + c;
        *(uint4*)&qh[r * HPI + c] = *(const uint4*)&gq[g];
        *(uint4*)&kh[r * HPI + c] = *(const uint4*)&g_k2h[g];
        *(uint4*)&rh[r * HPI + c] = *(const uint4*)&g_rah[g];
    }
    __syncthreads();

    const int a_row = lane & 15, a_kh = (lane >> 4) * 8;
    const int b_row = (lane & 7) + ((lane >> 4) << 3), b_kh = ((lane >> 3) & 1) * 8;

    // P1: logits = Q @ K2^T
    float lc[4][4];
    #pragma unroll
    for (int nt = 0; nt < 4; nt++)
        #pragma unroll
        for (int t = 0; t < 4; t++) lc[nt][t] = 0.0f;
    #pragma unroll
    for (int ks = 0; ks < 4; ks++) {
        uint32_t aa[4], bbf[4][2];
        LDSM4(aa[0], aa[1], aa[2], aa[3],
              smem_u32(&qh[(wm * 16 + a_row) * HPI + ks * 16 + a_kh]));
        #pragma unroll
        for (int j = 0; j < 2; j++)
            LDSM4(bbf[2*j][0], bbf[2*j][1], bbf[2*j+1][0], bbf[2*j+1][1],
                  smem_u32(&kh[(wn * 32 + j * 16 + b_row) * HPI + ks * 16 + b_kh]));
        #pragma unroll
        for (int nt = 0; nt < 4; nt++)
            MMA16816(lc[nt][0], lc[nt][1], lc[nt][2], lc[nt][3],
                     aa[0], aa[1], aa[2], aa[3], bbf[nt][0], bbf[nt][1]);
    }
    __syncthreads();

    {
        int crow = wm * 16 + (lane >> 2);
        int ccol = wn * 32 + (lane & 3) * 2;
        #pragma unroll
        for (int nt = 0; nt < 4; nt++) {
            int c0c = ccol + nt * 8;
            lg[crow * FPI + c0c]           = lc[nt][0] + ((c0c     >= crow)     ? NEGINF : 0.0f);
            lg[crow * FPI + c0c + 1]       = lc[nt][1] + ((c0c + 1 >= crow)     ? NEGINF : 0.0f);
            lg[(crow + 8) * FPI + c0c]     = lc[nt][2] + ((c0c     >= crow + 8) ? NEGINF : 0.0f);
            lg[(crow + 8) * FPI + c0c + 1] = lc[nt][3] + ((c0c + 1 >= crow + 8) ? NEGINF : 0.0f);
        }
    }
    __syncthreads();

    // P2: softmax stats + merge coefficients
    for (int r = wid; r < 64; r += 8) {
        float l0 = lg[r * FPI + lane];
        float l1 = lg[r * FPI + 32 + lane];
        float mg = warp_max(fmaxf(l0, l1));
        float e0 = __expf(l0 - mg), e1 = __expf(l1 - mg);
        float sg = warp_sum(e0 + e1);
        ph[r * HPI + lane]      = __float2half(e0);
        ph[r * HPI + 32 + lane] = __float2half(e1);
        if (lane == 0) {
            int t = b * SLEN + r * SEGLEN + l;
            float mlc = g_mloc[t * NH + h];
            float slc = g_sloc[t * NH + h];
            float m  = fmaxf(mlc, mg);
            float al = __expf(mlc - m);
            float ag = __expf(mg - m);
            float inv = 1.0f / (slc * al + sg * ag);
            s_cl[r] = al * inv;
            s_cg[r] = ag * inv;
        }
    }
    __syncthreads();

    // P3: ga = Pg @ RA
    float ga[4][4];
    #pragma unroll
    for (int nt = 0; nt < 4; nt++)
        #pragma unroll
        for (int t = 0; t < 4; t++) ga[nt][t] = 0.0f;
    #pragma unroll
    for (int ks = 0; ks < 4; ks++) {
        uint32_t pa[4], vb[4][2];
        LDSM4(pa[0], pa[1], pa[2], pa[3],
              smem_u32(&ph[(wm * 16 + a_row) * HPI + ks * 16 + a_kh]));
        #pragma unroll
        for (int j = 0; j < 2; j++)
            LDSM4T(vb[2*j][0], vb[2*j][1], vb[2*j+1][0], vb[2*j+1][1],
                   smem_u32(&rh[(ks * 16 + (lane & 15)) * HPI
                                + wn * 32 + j * 16 + (lane >> 4) * 8]));
        #pragma unroll
        for (int nt = 0; nt < 4; nt++)
            MMA16816(ga[nt][0], ga[nt][1], ga[nt][2], ga[nt][3],
                     pa[0], pa[1], pa[2], pa[3], vb[nt][0], vb[nt][1]);
    }

    // P4: merge with local branch
    {
        int orow = wm * 16 + (lane >> 2);
        #pragma unroll
        for (int nt = 0; nt < 4; nt++) {
            int col = wn * 32 + nt * 8 + (lane & 3) * 2;
            #pragma unroll
            for (int hh = 0; hh < 2; hh++) {
                int rr = orow + hh * 8;
                size_t base = (size_t)(b * SLEN + rr * SEGLEN + l) * DMODEL + h * DH + col;
                float2 la = __half22float2(*(__half2*)&g_lah[base]);
                float cl = s_cl[rr], cg = s_cg[rr];
                float ox = cl * la.x + cg * ga[nt][hh*2];
                float oy = cl * la.y + cg * ga[nt][hh*2+1];
                *(__half2*)&g_ah[base] = __floats2half2_rn(ox, oy);
            }
        }
    }
}

// ---------------------------------------------------------------------------
// LayerNorm: reads kt f32, writes normalized result as fp16
// ---------------------------------------------------------------------------
__global__ __launch_bounds__(256) void ln_k(const float* __restrict__ x,
                                            const float* __restrict__ sc,
                                            const float* __restrict__ bs,
                                            __half* __restrict__ oh)
{
    size_t row = blockIdx.x;
    const float* p = x + row * DMODEL;
    int c = threadIdx.x * 4;
    float4 v = *(const float4*)(p + c);
    float s  = v.x + v.y + v.z + v.w;
    float sq = v.x * v.x + v.y * v.y + v.z * v.z + v.w * v.w;
    s  = warp_sum(s);
    sq = warp_sum(sq);
    __shared__ float rs[8], rq[8];
    int warp = threadIdx.x >> 5, lane = threadIdx.x & 31;
    if (lane == 0) { rs[warp] = s; rq[warp] = sq; }
    __syncthreads();
    if (warp == 0) {
        float a = (lane < 8) ? rs[lane] : 0.0f;
        float b = (lane < 8) ? rq[lane] : 0.0f;
        a = warp_sum(a);
        b = warp_sum(b);
        if (lane == 0) { rs[0] = a; rq[0] = b; }
    }
    __syncthreads();
    float mean = rs[0] * (1.0f / DMODEL);
    float var  = rq[0] * (1.0f / DMODEL) - mean * mean;
    float inv  = rsqrtf(var + 1e-6f);
    float4 g = *(const float4*)(sc + c);
    float4 b4 = *(const float4*)(bs + c);
    v.x = (v.x - mean) * inv * g.x + b4.x;
    v.y = (v.y - mean) * inv * g.y + b4.y;
    v.z = (v.z - mean) * inv * g.z + b4.z;
    v.w = (v.w - mean) * inv * g.w + b4.w;
    size_t o = row * DMODEL + c;
    *(uint2*)(oh + o) = make_uint2(hb(v.x) | (hb(v.y) << 16),
                                   hb(v.z) | (hb(v.w) << 16));
}

// ---------------------------------------------------------------------------
// Host launcher
// ---------------------------------------------------------------------------
extern "C" void kernel_launch(void* const* d_in, const int* in_sizes, int n_in,
                              void* d_out, int out_size)
{
    const float* x    = (const float*)d_in[0];
    const float* Wq   = (const float*)d_in[1];
    const float* Wk   = (const float*)d_in[2];
    const float* Wv   = (const float*)d_in[3];
    const float* Wrow = (const float*)d_in[4];
    const float* lns  = (const float*)d_in[5];
    const float* lnb  = (const float*)d_in[6];
    const float* Wk2  = (const float*)d_in[7];
    const float* Wout = (const float*)d_in[8];
    float* out = (float*)d_out;

    float *kt;
    cudaGetSymbolAddress((void**)&kt, g_kt);

    __half *w16, *ah, *rah, *qkvh, *k2h;
    cudaGetSymbolAddress((void**)&w16,  g_w16);
    cudaGetSymbolAddress((void**)&ah,   g_ah);
    cudaGetSymbolAddress((void**)&rah,  g_rah);
    cudaGetSymbolAddress((void**)&qkvh, g_qkvh);
    cudaGetSymbolAddress((void**)&k2h,  g_k2h);
    const size_t MSZ = (size_t)NTOK * DMODEL;
    const size_t WSZ = (size_t)DMODEL * DMODEL;

    cudaFuncSetAttribute(attn_local_k,  cudaFuncAttributeMaxDynamicSharedMemorySize, ATT_SMEM);
    cudaFuncSetAttribute(attn_global_k, cudaFuncAttributeMaxDynamicSharedMemorySize, ATT_SMEM);
    cudaFuncSetAttribute(gemm_mma<true>,  cudaFuncAttributeMaxDynamicSharedMemorySize, GSMEM);
    cudaFuncSetAttribute(gemm_mma<false>, cudaFuncAttributeMaxDynamicSharedMemorySize, GSMEM);

    // weight prep: one launch for all 6 weights (Wq pre-scaled by 0.125)
    W6 w6;
    w6.p[0] = Wq; w6.p[1] = Wk; w6.p[2] = Wv;
    w6.p[3] = Wrow; w6.p[4] = Wk2; w6.p[5] = Wout;
    wprep_all<<<dim3(32, 32, 6), 256>>>(w6, w16);

    dim3 bt(256);
    const int ACONV_G = (NTOK * DMODEL) / (256 * 4);

    // x -> fp16, then fused QKV projection (fp16 out), persistent grid
    aconv_k<<<ACONV_G, 256>>>(x, ah);
    gemm_mma<true><<<GGRID, bt, GSMEM>>>(ah, w16, nullptr, qkvh, MSZ, 24, 3072);

    // local attention (tensor-core)
    attn_local_k<<<NBATCH * NSEG * NH, 256, ATT_SMEM>>>();

    // key_row = ra @ Wrow + x (f32) ; LN -> fp16 ; @ Wk2 (fp16 out)
    gemm_mma<false><<<GGRID, bt, GSMEM>>>(rah, w16 + 3 * WSZ, x, kt, 0, 8, 1024);
    ln_k<<<NTOK, 256>>>(kt, lns, lnb, ah);
    gemm_mma<true><<<GGRID, bt, GSMEM>>>(ah, w16 + 4 * WSZ, nullptr, k2h, 0, 8, 1024);

    // global attention + merge (tensor-core)
    attn_global_k<<<NBATCH * SEGLEN * NH, 256, ATT_SMEM>>>();

    // output projection (f32 out)
    gemm_mma<false><<<GGRID, bt, GSMEM>>>(ah, w16 + 5 * WSZ, nullptr, out, 0, 8, 1024);
}